// round 3
// baseline (speedup 1.0000x reference)
#include <cuda_runtime.h>
#include <math.h>

#define BSZ 4096
#define CSZ 16000
#define C4  4000
#define NM1 15999.0f
#define LOG2E 1.4426950408889634f
#define NCHUNK 8
#define RCHUNK 512

// ---------------- scratch (device globals) ----------------------------------
__device__ float  g_c[2][BSZ];           // -log2(Z)
__device__ float  g_m[2][BSZ];           // row max
__device__ int    g_cnt[2][BSZ][10];
__device__ int    g_amax[2][BSZ];
__device__ float  g_s1[CSZ], g_s2[CSZ], g_t1[CSZ], g_t2[CSZ], g_st[CSZ];
__device__ double g_pintra[64], g_psp[16], g_peq[16];

static __device__ __forceinline__ float ex2f(float x) {
    float y;
    asm("ex2.approx.f32 %0, %1;" : "=f"(y) : "f"(x));
    return y;
}

// ---------------- kernel 0: init --------------------------------------------
__global__ void k_init() {
    int i = blockIdx.x * blockDim.x + threadIdx.x;
    if (i < CSZ) {
        g_s1[i] = 0.f; g_s2[i] = 0.f; g_t1[i] = 0.f; g_t2[i] = 0.f; g_st[i] = 0.f;
    }
    if (i < 2 * BSZ) (&g_amax[0][0])[i] = 0x7FFFFFFF;
}

// ---------------- kernel 1: row pass (chunk) ---------------------------------
__global__ void __launch_bounds__(256) k_rowstats(const float* __restrict__ zs,
                                                  const float* __restrict__ zt,
                                                  int r0) {
    const int b = r0 + blockIdx.x;
    const int t = blockIdx.y;
    const float* row = (t == 0 ? zs : zt) + (size_t)b * CSZ;
    const float4* row4 = (const float4*)row;

    float u[10];
#pragma unroll
    for (int j = 0; j < 10; j++) u[j] = row[j];   // broadcast, L1 hit

    float mx = -1e30f;
    float sm0 = 0.f, sm1 = 0.f, sm2 = 0.f, sm3 = 0.f;
    int cnt[10];
#pragma unroll
    for (int j = 0; j < 10; j++) cnt[j] = 0;

#pragma unroll 5
    for (int it = 0; it < 15; it++) {
        float4 v = row4[threadIdx.x + it * 256];
        sm0 += ex2f(v.x * LOG2E);
        sm1 += ex2f(v.y * LOG2E);
        sm2 += ex2f(v.z * LOG2E);
        sm3 += ex2f(v.w * LOG2E);
        mx = fmaxf(mx, fmaxf(fmaxf(v.x, v.y), fmaxf(v.z, v.w)));
#pragma unroll
        for (int j = 0; j < 10; j++)
            cnt[j] += (int)(v.x < u[j]) + (int)(v.y < u[j]) +
                      (int)(v.z < u[j]) + (int)(v.w < u[j]);
    }
    if (threadIdx.x < 160) {                        // tail: 3840..3999
        float4 v = row4[threadIdx.x + 3840];
        sm0 += ex2f(v.x * LOG2E);
        sm1 += ex2f(v.y * LOG2E);
        sm2 += ex2f(v.z * LOG2E);
        sm3 += ex2f(v.w * LOG2E);
        mx = fmaxf(mx, fmaxf(fmaxf(v.x, v.y), fmaxf(v.z, v.w)));
#pragma unroll
        for (int j = 0; j < 10; j++)
            cnt[j] += (int)(v.x < u[j]) + (int)(v.y < u[j]) +
                      (int)(v.z < u[j]) + (int)(v.w < u[j]);
    }
    float sm = (sm0 + sm1) + (sm2 + sm3);

    const unsigned FULL = 0xffffffffu;
#pragma unroll
    for (int o = 16; o; o >>= 1) {
        mx = fmaxf(mx, __shfl_xor_sync(FULL, mx, o));
        sm += __shfl_xor_sync(FULL, sm, o);
    }
#pragma unroll
    for (int j = 0; j < 10; j++) cnt[j] = __reduce_add_sync(FULL, cnt[j]);

    __shared__ float smx[8], ssm[8];
    __shared__ int scnt[8][10];
    int w = threadIdx.x >> 5, lane = threadIdx.x & 31;
    if (lane == 0) {
        smx[w] = mx; ssm[w] = sm;
#pragma unroll
        for (int j = 0; j < 10; j++) scnt[w][j] = cnt[j];
    }
    __syncthreads();
    if (threadIdx.x == 0) {
#pragma unroll
        for (int ww = 1; ww < 8; ww++) {
            mx = fmaxf(mx, smx[ww]);
            sm += ssm[ww];
#pragma unroll
            for (int j = 0; j < 10; j++) cnt[j] += scnt[ww][j];
        }
        g_m[t][b] = mx;
        g_c[t][b] = -log2f(sm);
#pragma unroll
        for (int j = 0; j < 10; j++) g_cnt[t][b][j] = cnt[j];
    }
}

// ---------------- kernel 3: column pass (chunk; intra stats + argmax) --------
// grid (16, 16): 1024 cols per x-block, 32 rows per y-block.
__global__ void __launch_bounds__(256) k_colstats(const float* __restrict__ zs,
                                                  const float* __restrict__ zt,
                                                  int rbase) {
    const int c = blockIdx.x * 1024 + threadIdx.x * 4;
    if (c >= CSZ) return;
    const int r0 = rbase + blockIdx.y * 32;

    float a1[4] = {0, 0, 0, 0}, a2[4] = {0, 0, 0, 0};
    float b1[4] = {0, 0, 0, 0}, b2[4] = {0, 0, 0, 0};
    float ab[4] = {0, 0, 0, 0};

#pragma unroll 4
    for (int rr = 0; rr < 32; rr++) {
        const int r = r0 + rr;
        const float cs = g_c[0][r], ct = g_c[1][r];   // uniform
        const float ms = g_m[0][r], mt = g_m[1][r];
        const float4 xs = __ldcs((const float4*)(zs + (size_t)r * CSZ + c));
        const float4 xt = __ldcs((const float4*)(zt + (size_t)r * CSZ + c));
#pragma unroll
        for (int k = 0; k < 4; k++) {
            float xsk = (k == 0 ? xs.x : k == 1 ? xs.y : k == 2 ? xs.z : xs.w);
            float xtk = (k == 0 ? xt.x : k == 1 ? xt.y : k == 2 ? xt.z : xt.w);
            float ys = ex2f(fmaf(xsk, LOG2E, cs));
            float yt = ex2f(fmaf(xtk, LOG2E, ct));
            a1[k] += ys; a2[k] = fmaf(ys, ys, a2[k]);
            b1[k] += yt; b2[k] = fmaf(yt, yt, b2[k]);
            ab[k] = fmaf(ys, yt, ab[k]);
            if (xsk == ms) atomicMin(&g_amax[0][r], c + k);
            if (xtk == mt) atomicMin(&g_amax[1][r], c + k);
        }
    }
#pragma unroll
    for (int k = 0; k < 4; k++) {
        atomicAdd(&g_s1[c + k], a1[k]);
        atomicAdd(&g_s2[c + k], a2[k]);
        atomicAdd(&g_t1[c + k], b1[k]);
        atomicAdd(&g_t2[c + k], b2[k]);
        atomicAdd(&g_st[c + k], ab[k]);
    }
}

// ---------------- kernel 4: parallel partial reductions ----------------------
__global__ void __launch_bounds__(256) k_partial() {
    const int bid = blockIdx.x;
    const int tid = threadIdx.x;
    __shared__ double sh0[256], sh1[256];

    if (bid < 64) {
        double intra = 0.0;
        const float invB = 1.f / (float)BSZ;
        int c = bid * 250 + tid;
        if (tid < 250) {
            float s1 = g_s1[c], s2 = g_s2[c], t1 = g_t1[c], t2 = g_t2[c], st = g_st[c];
            float num = st - s1 * t1 * invB;
            float vs = s2 - s1 * s1 * invB;
            float vt = t2 - t1 * t1 * invB;
            float den = sqrtf(fmaxf(vs, 0.f)) * sqrtf(fmaxf(vt, 0.f)) + 1e-8f;
            intra = (double)(num / den);
        }
        sh0[tid] = intra; sh1[tid] = 0.0;
        __syncthreads();
        for (int s = 128; s; s >>= 1) {
            if (tid < s) sh0[tid] += sh0[tid + s];
            __syncthreads();
        }
        if (tid == 0) g_pintra[bid] = sh0[0];
    } else {
        const int b = (bid - 64) * 256 + tid;
        const int js = g_amax[0][b], jt = g_amax[1][b];
        double eq = (js == jt) ? 1.0 : 0.0;

        int ms[10], mt[10];
        bool ks[10], kt[10];
        float Ds = 0.f, Qs = 0.f, Dt = 0.f, Qt = 0.f;
#pragma unroll
        for (int i = 0; i < 10; i++) {
            int p = g_cnt[0][b][i];
            ks[i] = (p != js);
            ms[i] = p - (p > js ? 1 : 0);
            float v = (float)(10 - i);
            if (ks[i]) { Ds += v; Qs += v * v; }
            p = g_cnt[1][b][i];
            kt[i] = (p != jt);
            mt[i] = p - (p > jt ? 1 : 0);
            if (kt[i]) { Dt += v; Qt += v * v; }
        }
        float X = 0.f;
#pragma unroll
        for (int i = 0; i < 10; i++) {
#pragma unroll
            for (int k2 = 0; k2 < 10; k2++) {
                if (ks[i] && kt[k2] && (ms[i] == mt[k2]))
                    X += (float)(10 - i) * (float)(10 - k2);
            }
        }
        float num = X - Ds * Dt / NM1;
        float den = sqrtf(fmaxf(Qs - Ds * Ds / NM1, 0.f)) *
                    sqrtf(fmaxf(Qt - Dt * Dt / NM1, 0.f)) + 1e-8f;
        double sp = (double)(num / den);

        sh0[tid] = sp; sh1[tid] = eq;
        __syncthreads();
        for (int s = 128; s; s >>= 1) {
            if (tid < s) { sh0[tid] += sh0[tid + s]; sh1[tid] += sh1[tid + s]; }
            __syncthreads();
        }
        if (tid == 0) { g_psp[bid - 64] = sh0[0]; g_peq[bid - 64] = sh1[0]; }
    }
}

// ---------------- kernel 5: combine ------------------------------------------
__global__ void __launch_bounds__(128) k_combine(float* __restrict__ out) {
    const int tid = threadIdx.x;
    __shared__ double sh0[128], sh1[128], sh2[128];
    double a = 0.0, b = 0.0, c = 0.0;
    if (tid < 64) a = g_pintra[tid];
    if (tid < 16) { b = g_psp[tid]; c = g_peq[tid]; }
    sh0[tid] = a; sh1[tid] = b; sh2[tid] = c;
    __syncthreads();
    for (int s = 64; s; s >>= 1) {
        if (tid < s) {
            sh0[tid] += sh0[tid + s];
            sh1[tid] += sh1[tid + s];
            sh2[tid] += sh2[tid + s];
        }
        __syncthreads();
    }
    if (tid == 0) {
        double inter_loss = 1.0 - (sh2[0] / (double)BSZ + sh1[0] / (double)BSZ);
        double intra_loss = 1.0 - sh0[0] / (double)CSZ;
        out[0] = (float)(inter_loss + intra_loss);
    }
}

// ---------------- launch: chunked two-stream pipeline ------------------------
extern "C" void kernel_launch(void* const* d_in, const int* in_sizes, int n_in,
                              void* d_out, int out_size) {
    const float* zs = (const float*)d_in[0];
    const float* zt = (const float*)d_in[1];

    // Created once on the first (non-captured) correctness call; reused during
    // graph capture. No device-memory allocation involved.
    static cudaStream_t s2 = nullptr;
    static cudaEvent_t evR[NCHUNK];
    static cudaEvent_t evDone = nullptr;
    if (s2 == nullptr) {
        cudaStreamCreateWithFlags(&s2, cudaStreamNonBlocking);
        for (int i = 0; i < NCHUNK; i++)
            cudaEventCreateWithFlags(&evR[i], cudaEventDisableTiming);
        cudaEventCreateWithFlags(&evDone, cudaEventDisableTiming);
    }

    k_init<<<63, 256>>>();

    for (int i = 0; i < NCHUNK; i++) {
        k_rowstats<<<dim3(RCHUNK, 2), 256>>>(zs, zt, i * RCHUNK);
        cudaEventRecord(evR[i], 0);
    }
    for (int i = 0; i < NCHUNK; i++) {
        cudaStreamWaitEvent(s2, evR[i], 0);
        k_colstats<<<dim3(16, 16), 256, 0, s2>>>(zs, zt, i * RCHUNK);
    }
    cudaEventRecord(evDone, s2);
    cudaStreamWaitEvent(0, evDone, 0);

    k_partial<<<80, 256>>>();
    k_combine<<<1, 128>>>((float*)d_out);
}

// round 4
// speedup vs baseline: 1.5137x; 1.5137x over previous
#include <cuda_runtime.h>
#include <math.h>

#define BSZ 4096
#define CSZ 16000
#define C4  4000
#define NM1 15999.0f
#define LOG2E 1.4426950408889634f

// ---------------- scratch (device globals) ----------------------------------
__device__ float  g_c[2][BSZ];           // -log2(Z)
__device__ float  g_m[2][BSZ];           // row max
__device__ int    g_cnt[2][BSZ][10];     // j<5 written by rowstats, j>=5 atomically by colstats
__device__ int    g_amax[2][BSZ];
__device__ float  g_s1[CSZ], g_s2[CSZ], g_t1[CSZ], g_t2[CSZ], g_st[CSZ];
__device__ double g_pintra[64], g_psp[16], g_peq[16];

static __device__ __forceinline__ float ex2f(float x) {
    float y;
    asm("ex2.approx.f32 %0, %1;" : "=f"(y) : "f"(x));
    return y;
}

// ---------------- kernel 0: init --------------------------------------------
__global__ void k_init() {
    int i = blockIdx.x * blockDim.x + threadIdx.x;
    if (i < CSZ) {
        g_s1[i] = 0.f; g_s2[i] = 0.f; g_t1[i] = 0.f; g_t2[i] = 0.f; g_st[i] = 0.f;
    }
    if (i < 2 * BSZ) (&g_amax[0][0])[i] = 0x7FFFFFFF;
    // zero the colstats-side count slots (j = 5..9)
    if (i < 2 * BSZ * 5) {
        int t = i / (BSZ * 5);
        int r = (i / 5) % BSZ;
        int j = i % 5;
        g_cnt[t][r][5 + j] = 0;
    }
}

// ---------------- kernel 1: row pass (max, sum-exp, 5 rank counts) -----------
__global__ void __launch_bounds__(256) k_rowstats(const float* __restrict__ zs,
                                                  const float* __restrict__ zt) {
    const int b = blockIdx.x;
    const int t = blockIdx.y;
    const float* row = (t == 0 ? zs : zt) + (size_t)b * CSZ;
    const float4* row4 = (const float4*)row;

    float u[5];
#pragma unroll
    for (int j = 0; j < 5; j++) u[j] = row[j];   // broadcast, L1 hit

    float mx = -1e30f;
    float sm0 = 0.f, sm1 = 0.f, sm2 = 0.f, sm3 = 0.f;
    int cnt[5];
#pragma unroll
    for (int j = 0; j < 5; j++) cnt[j] = 0;

#pragma unroll 4
    for (int i = threadIdx.x; i < C4; i += 256) {
        float4 v = __ldcs(row4 + i);
        sm0 += ex2f(v.x * LOG2E);
        sm1 += ex2f(v.y * LOG2E);
        sm2 += ex2f(v.z * LOG2E);
        sm3 += ex2f(v.w * LOG2E);
        mx = fmaxf(mx, fmaxf(fmaxf(v.x, v.y), fmaxf(v.z, v.w)));
#pragma unroll
        for (int j = 0; j < 5; j++)
            cnt[j] += (int)(v.x < u[j]) + (int)(v.y < u[j]) +
                      (int)(v.z < u[j]) + (int)(v.w < u[j]);
    }
    float sm = (sm0 + sm1) + (sm2 + sm3);

    const unsigned FULL = 0xffffffffu;
#pragma unroll
    for (int o = 16; o; o >>= 1) {
        mx = fmaxf(mx, __shfl_xor_sync(FULL, mx, o));
        sm += __shfl_xor_sync(FULL, sm, o);
    }
#pragma unroll
    for (int j = 0; j < 5; j++) cnt[j] = __reduce_add_sync(FULL, cnt[j]);

    __shared__ float smx[8], ssm[8];
    __shared__ int scnt[8][5];
    int w = threadIdx.x >> 5, lane = threadIdx.x & 31;
    if (lane == 0) {
        smx[w] = mx; ssm[w] = sm;
#pragma unroll
        for (int j = 0; j < 5; j++) scnt[w][j] = cnt[j];
    }
    __syncthreads();
    if (threadIdx.x == 0) {
#pragma unroll
        for (int ww = 1; ww < 8; ww++) {
            mx = fmaxf(mx, smx[ww]);
            sm += ssm[ww];
#pragma unroll
            for (int j = 0; j < 5; j++) cnt[j] += scnt[ww][j];
        }
        g_m[t][b] = mx;
        g_c[t][b] = -log2f(sm);
#pragma unroll
        for (int j = 0; j < 5; j++) g_cnt[t][b][j] = cnt[j];
    }
}

// ---------------- kernel 2: column pass (intra stats + argmax + counts 5..9) -
// grid (16, 128): 1024 cols per x-block, 32 rows per y-block.
__global__ void __launch_bounds__(256) k_colstats(const float* __restrict__ zs,
                                                  const float* __restrict__ zt) {
    const int c = blockIdx.x * 1024 + threadIdx.x * 4;
    const int r0 = blockIdx.y * 32;
    const int lane = threadIdx.x & 31;

    // Per-row thresholds u[5..9] for both tensors, staged in smem.
    __shared__ float sh_us[32][8];   // [row][0..4]=u5..u9, padded
    __shared__ float sh_ut[32][8];
    {
        int tid = threadIdx.x;
        if (tid < 160) {
            int rr = tid / 5, j = tid % 5;
            sh_us[rr][j] = zs[(size_t)(r0 + rr) * CSZ + 5 + j];
        } else if (tid < 320) {
            int q = tid - 160;
            int rr = q / 5, j = q % 5;
            sh_ut[rr][j] = zt[(size_t)(r0 + rr) * CSZ + 5 + j];
        }
    }
    __syncthreads();
    if (c >= CSZ) return;

    float a1[4] = {0, 0, 0, 0}, a2[4] = {0, 0, 0, 0};
    float b1[4] = {0, 0, 0, 0}, b2[4] = {0, 0, 0, 0};
    float ab[4] = {0, 0, 0, 0};

    for (int rr = 0; rr < 32; rr++) {
        const int r = r0 + rr;
        const float cs = g_c[0][r], ct = g_c[1][r];   // uniform
        const float ms = g_m[0][r], mt = g_m[1][r];
        const float4 xs = __ldcs((const float4*)(zs + (size_t)r * CSZ + c));
        const float4 xt = __ldcs((const float4*)(zt + (size_t)r * CSZ + c));

        int cs5[5] = {0, 0, 0, 0, 0}, ct5[5] = {0, 0, 0, 0, 0};
        float us[5], ut[5];
#pragma unroll
        for (int j = 0; j < 5; j++) { us[j] = sh_us[rr][j]; ut[j] = sh_ut[rr][j]; }

#pragma unroll
        for (int k = 0; k < 4; k++) {
            float xsk = (k == 0 ? xs.x : k == 1 ? xs.y : k == 2 ? xs.z : xs.w);
            float xtk = (k == 0 ? xt.x : k == 1 ? xt.y : k == 2 ? xt.z : xt.w);
            float ys = ex2f(fmaf(xsk, LOG2E, cs));
            float yt = ex2f(fmaf(xtk, LOG2E, ct));
            a1[k] += ys; a2[k] = fmaf(ys, ys, a2[k]);
            b1[k] += yt; b2[k] = fmaf(yt, yt, b2[k]);
            ab[k] = fmaf(ys, yt, ab[k]);
            if (xsk == ms) atomicMin(&g_amax[0][r], c + k);
            if (xtk == mt) atomicMin(&g_amax[1][r], c + k);
#pragma unroll
            for (int j = 0; j < 5; j++) {
                cs5[j] += (xsk < us[j]);
                ct5[j] += (xtk < ut[j]);
            }
        }

        // warp-level reduce of this row's partial counts, lane 0 commits
        const unsigned FULL = 0xffffffffu;
#pragma unroll
        for (int j = 0; j < 5; j++) {
            int vs = __reduce_add_sync(FULL, cs5[j]);
            int vt = __reduce_add_sync(FULL, ct5[j]);
            if (lane == 0) {
                atomicAdd(&g_cnt[0][r][5 + j], vs);
                atomicAdd(&g_cnt[1][r][5 + j], vt);
            }
        }
    }
#pragma unroll
    for (int k = 0; k < 4; k++) {
        atomicAdd(&g_s1[c + k], a1[k]);
        atomicAdd(&g_s2[c + k], a2[k]);
        atomicAdd(&g_t1[c + k], b1[k]);
        atomicAdd(&g_t2[c + k], b2[k]);
        atomicAdd(&g_st[c + k], ab[k]);
    }
}

// ---------------- kernel 3: parallel partial reductions ----------------------
__global__ void __launch_bounds__(256) k_partial() {
    const int bid = blockIdx.x;
    const int tid = threadIdx.x;
    __shared__ double sh0[256], sh1[256];

    if (bid < 64) {
        double intra = 0.0;
        const float invB = 1.f / (float)BSZ;
        int c = bid * 250 + tid;
        if (tid < 250) {
            float s1 = g_s1[c], s2 = g_s2[c], t1 = g_t1[c], t2 = g_t2[c], st = g_st[c];
            float num = st - s1 * t1 * invB;
            float vs = s2 - s1 * s1 * invB;
            float vt = t2 - t1 * t1 * invB;
            float den = sqrtf(fmaxf(vs, 0.f)) * sqrtf(fmaxf(vt, 0.f)) + 1e-8f;
            intra = (double)(num / den);
        }
        sh0[tid] = intra; sh1[tid] = 0.0;
        __syncthreads();
        for (int s = 128; s; s >>= 1) {
            if (tid < s) sh0[tid] += sh0[tid + s];
            __syncthreads();
        }
        if (tid == 0) g_pintra[bid] = sh0[0];
    } else {
        const int b = (bid - 64) * 256 + tid;
        const int js = g_amax[0][b], jt = g_amax[1][b];
        double eq = (js == jt) ? 1.0 : 0.0;

        int ms[10], mt[10];
        bool ks[10], kt[10];
        float Ds = 0.f, Qs = 0.f, Dt = 0.f, Qt = 0.f;
#pragma unroll
        for (int i = 0; i < 10; i++) {
            int p = g_cnt[0][b][i];
            ks[i] = (p != js);
            ms[i] = p - (p > js ? 1 : 0);
            float v = (float)(10 - i);
            if (ks[i]) { Ds += v; Qs += v * v; }
            p = g_cnt[1][b][i];
            kt[i] = (p != jt);
            mt[i] = p - (p > jt ? 1 : 0);
            if (kt[i]) { Dt += v; Qt += v * v; }
        }
        float X = 0.f;
#pragma unroll
        for (int i = 0; i < 10; i++) {
#pragma unroll
            for (int k2 = 0; k2 < 10; k2++) {
                if (ks[i] && kt[k2] && (ms[i] == mt[k2]))
                    X += (float)(10 - i) * (float)(10 - k2);
            }
        }
        float num = X - Ds * Dt / NM1;
        float den = sqrtf(fmaxf(Qs - Ds * Ds / NM1, 0.f)) *
                    sqrtf(fmaxf(Qt - Dt * Dt / NM1, 0.f)) + 1e-8f;
        double sp = (double)(num / den);

        sh0[tid] = sp; sh1[tid] = eq;
        __syncthreads();
        for (int s = 128; s; s >>= 1) {
            if (tid < s) { sh0[tid] += sh0[tid + s]; sh1[tid] += sh1[tid + s]; }
            __syncthreads();
        }
        if (tid == 0) { g_psp[bid - 64] = sh0[0]; g_peq[bid - 64] = sh1[0]; }
    }
}

// ---------------- kernel 4: combine ------------------------------------------
__global__ void __launch_bounds__(128) k_combine(float* __restrict__ out) {
    const int tid = threadIdx.x;
    __shared__ double sh0[128], sh1[128], sh2[128];
    double a = 0.0, b = 0.0, c = 0.0;
    if (tid < 64) a = g_pintra[tid];
    if (tid < 16) { b = g_psp[tid]; c = g_peq[tid]; }
    sh0[tid] = a; sh1[tid] = b; sh2[tid] = c;
    __syncthreads();
    for (int s = 64; s; s >>= 1) {
        if (tid < s) {
            sh0[tid] += sh0[tid + s];
            sh1[tid] += sh1[tid + s];
            sh2[tid] += sh2[tid + s];
        }
        __syncthreads();
    }
    if (tid == 0) {
        double inter_loss = 1.0 - (sh2[0] / (double)BSZ + sh1[0] / (double)BSZ);
        double intra_loss = 1.0 - sh0[0] / (double)CSZ;
        out[0] = (float)(inter_loss + intra_loss);
    }
}

// ---------------- launch ------------------------------------------------------
extern "C" void kernel_launch(void* const* d_in, const int* in_sizes, int n_in,
                              void* d_out, int out_size) {
    const float* zs = (const float*)d_in[0];
    const float* zt = (const float*)d_in[1];

    k_init<<<(2 * BSZ * 5 + 255) / 256, 256>>>();

    dim3 g1(BSZ, 2);
    k_rowstats<<<g1, 256>>>(zs, zt);

    dim3 g2(16, 128);
    k_colstats<<<g2, 256>>>(zs, zt);

    k_partial<<<80, 256>>>();
    k_combine<<<1, 128>>>((float*)d_out);
}

// round 6
// speedup vs baseline: 1.7609x; 1.1633x over previous
#include <cuda_runtime.h>
#include <math.h>

#define BSZ 4096
#define CSZ 16000
#define C4  4000
#define NM1 15999.0f
#define LOG2E 1.4426950408889634f

// ---------------- scratch (device globals) ----------------------------------
__device__ float  g_c[2][BSZ];           // -log2(Z)
__device__ float  g_m[2][BSZ];           // row max
__device__ int    g_cnt[2][BSZ][10];
__device__ int    g_amax[2][BSZ];
__device__ float  g_s1[CSZ], g_s2[CSZ], g_t1[CSZ], g_t2[CSZ], g_st[CSZ];
__device__ double g_pintra[64], g_psp[16], g_peq[16];

static __device__ __forceinline__ float ex2f(float x) {
    float y;
    asm("ex2.approx.f32 %0, %1;" : "=f"(y) : "f"(x));
    return y;
}

// ---------------- kernel 1: row pass (max, sum-exp, 10 rank counts) ----------
// Also performs the scratch init that used to be k_init (grid-order safe:
// all init writes land before this kernel completes; colstats runs after).
__global__ void __launch_bounds__(256) k_rowstats(const float* __restrict__ zs,
                                                  const float* __restrict__ zt) {
    const int b = blockIdx.x;
    const int t = blockIdx.y;

    // ---- folded init ----
    if (threadIdx.x == 10) g_amax[t][b] = 0x7FFFFFFF;
    if (threadIdx.x < 10) {
        int gid = b * 2 + t;
        int i = gid * 10 + threadIdx.x;
        if (i < CSZ) {
            g_s1[i] = 0.f; g_s2[i] = 0.f; g_t1[i] = 0.f; g_t2[i] = 0.f; g_st[i] = 0.f;
        }
    }

    const float* row = (t == 0 ? zs : zt) + (size_t)b * CSZ;
    const float4* row4 = (const float4*)row;

    float u[10];
#pragma unroll
    for (int j = 0; j < 10; j++) u[j] = row[j];   // broadcast, L1 hit

    float mx = -1e30f;
    float sm0 = 0.f, sm1 = 0.f, sm2 = 0.f, sm3 = 0.f;
    int cnt[10];
#pragma unroll
    for (int j = 0; j < 10; j++) cnt[j] = 0;

#pragma unroll 5
    for (int i = threadIdx.x; i < C4; i += 256) {
        float4 v = __ldcs(row4 + i);
        sm0 += ex2f(v.x * LOG2E);
        sm1 += ex2f(v.y * LOG2E);
        sm2 += ex2f(v.z * LOG2E);
        sm3 += ex2f(v.w * LOG2E);
        mx = fmaxf(mx, fmaxf(fmaxf(v.x, v.y), fmaxf(v.z, v.w)));
#pragma unroll
        for (int j = 0; j < 10; j++)
            cnt[j] += (int)(v.x < u[j]) + (int)(v.y < u[j]) +
                      (int)(v.z < u[j]) + (int)(v.w < u[j]);
    }
    float sm = (sm0 + sm1) + (sm2 + sm3);

    const unsigned FULL = 0xffffffffu;
#pragma unroll
    for (int o = 16; o; o >>= 1) {
        mx = fmaxf(mx, __shfl_xor_sync(FULL, mx, o));
        sm += __shfl_xor_sync(FULL, sm, o);
    }
#pragma unroll
    for (int j = 0; j < 10; j++) cnt[j] = __reduce_add_sync(FULL, cnt[j]);

    __shared__ float smx[8], ssm[8];
    __shared__ int scnt[8][10];
    int w = threadIdx.x >> 5, lane = threadIdx.x & 31;
    if (lane == 0) {
        smx[w] = mx; ssm[w] = sm;
#pragma unroll
        for (int j = 0; j < 10; j++) scnt[w][j] = cnt[j];
    }
    __syncthreads();
    if (threadIdx.x == 0) {
#pragma unroll
        for (int ww = 1; ww < 8; ww++) {
            mx = fmaxf(mx, smx[ww]);
            sm += ssm[ww];
#pragma unroll
            for (int j = 0; j < 10; j++) cnt[j] += scnt[ww][j];
        }
        g_m[t][b] = mx;
        g_c[t][b] = -log2f(sm);
#pragma unroll
        for (int j = 0; j < 10; j++) g_cnt[t][b][j] = cnt[j];
    }
}

// ---------------- kernel 2: column pass (intra stats + argmax) ---------------
// grid (16, 128): 1024 cols per x-block, 32 rows per y-block.
// Row-block order REVERSED so the first scheduled blocks hit the rows that
// rowstats streamed last (still resident in L2).
__global__ void __launch_bounds__(256) k_colstats(const float* __restrict__ zs,
                                                  const float* __restrict__ zt) {
    const int c = blockIdx.x * 1024 + threadIdx.x * 4;
    if (c >= CSZ) return;
    const int r0 = (127 - blockIdx.y) * 32;

    float a1[4] = {0, 0, 0, 0}, a2[4] = {0, 0, 0, 0};
    float b1[4] = {0, 0, 0, 0}, b2[4] = {0, 0, 0, 0};
    float ab[4] = {0, 0, 0, 0};

#pragma unroll 4
    for (int rr = 0; rr < 32; rr++) {
        const int r = r0 + rr;
        const float cs = g_c[0][r], ct = g_c[1][r];   // uniform
        const float ms = g_m[0][r], mt = g_m[1][r];
        const float4 xs = __ldcs((const float4*)(zs + (size_t)r * CSZ + c));
        const float4 xt = __ldcs((const float4*)(zt + (size_t)r * CSZ + c));
#pragma unroll
        for (int k = 0; k < 4; k++) {
            float xsk = (k == 0 ? xs.x : k == 1 ? xs.y : k == 2 ? xs.z : xs.w);
            float xtk = (k == 0 ? xt.x : k == 1 ? xt.y : k == 2 ? xt.z : xt.w);
            float ys = ex2f(fmaf(xsk, LOG2E, cs));
            float yt = ex2f(fmaf(xtk, LOG2E, ct));
            a1[k] += ys; a2[k] = fmaf(ys, ys, a2[k]);
            b1[k] += yt; b2[k] = fmaf(yt, yt, b2[k]);
            ab[k] = fmaf(ys, yt, ab[k]);
            if (xsk == ms) atomicMin(&g_amax[0][r], c + k);
            if (xtk == mt) atomicMin(&g_amax[1][r], c + k);
        }
    }
#pragma unroll
    for (int k = 0; k < 4; k++) {
        atomicAdd(&g_s1[c + k], a1[k]);
        atomicAdd(&g_s2[c + k], a2[k]);
        atomicAdd(&g_t1[c + k], b1[k]);
        atomicAdd(&g_t2[c + k], b2[k]);
        atomicAdd(&g_st[c + k], ab[k]);
    }
}

// ---------------- kernel 3: parallel partial reductions ----------------------
__global__ void __launch_bounds__(256) k_partial() {
    const int bid = blockIdx.x;
    const int tid = threadIdx.x;
    __shared__ double sh0[256], sh1[256];

    if (bid < 64) {
        double intra = 0.0;
        const float invB = 1.f / (float)BSZ;
        int c = bid * 250 + tid;
        if (tid < 250) {
            float s1 = g_s1[c], s2 = g_s2[c], t1 = g_t1[c], t2 = g_t2[c], st = g_st[c];
            float num = st - s1 * t1 * invB;
            float vs = s2 - s1 * s1 * invB;
            float vt = t2 - t1 * t1 * invB;
            float den = sqrtf(fmaxf(vs, 0.f)) * sqrtf(fmaxf(vt, 0.f)) + 1e-8f;
            intra = (double)(num / den);
        }
        sh0[tid] = intra; sh1[tid] = 0.0;
        __syncthreads();
        for (int s = 128; s; s >>= 1) {
            if (tid < s) sh0[tid] += sh0[tid + s];
            __syncthreads();
        }
        if (tid == 0) g_pintra[bid] = sh0[0];
    } else {
        const int b = (bid - 64) * 256 + tid;
        const int js = g_amax[0][b], jt = g_amax[1][b];
        double eq = (js == jt) ? 1.0 : 0.0;

        int ms[10], mt[10];
        bool ks[10], kt[10];
        float Ds = 0.f, Qs = 0.f, Dt = 0.f, Qt = 0.f;
#pragma unroll
        for (int i = 0; i < 10; i++) {
            int p = g_cnt[0][b][i];
            ks[i] = (p != js);
            ms[i] = p - (p > js ? 1 : 0);
            float v = (float)(10 - i);
            if (ks[i]) { Ds += v; Qs += v * v; }
            p = g_cnt[1][b][i];
            kt[i] = (p != jt);
            mt[i] = p - (p > jt ? 1 : 0);
            if (kt[i]) { Dt += v; Qt += v * v; }
        }
        float X = 0.f;
#pragma unroll
        for (int i = 0; i < 10; i++) {
#pragma unroll
            for (int k2 = 0; k2 < 10; k2++) {
                if (ks[i] && kt[k2] && (ms[i] == mt[k2]))
                    X += (float)(10 - i) * (float)(10 - k2);
            }
        }
        float num = X - Ds * Dt / NM1;
        float den = sqrtf(fmaxf(Qs - Ds * Ds / NM1, 0.f)) *
                    sqrtf(fmaxf(Qt - Dt * Dt / NM1, 0.f)) + 1e-8f;
        double sp = (double)(num / den);

        sh0[tid] = sp; sh1[tid] = eq;
        __syncthreads();
        for (int s = 128; s; s >>= 1) {
            if (tid < s) { sh0[tid] += sh0[tid + s]; sh1[tid] += sh1[tid + s]; }
            __syncthreads();
        }
        if (tid == 0) { g_psp[bid - 64] = sh0[0]; g_peq[bid - 64] = sh1[0]; }
    }
}

// ---------------- kernel 4: combine ------------------------------------------
__global__ void __launch_bounds__(128) k_combine(float* __restrict__ out) {
    const int tid = threadIdx.x;
    __shared__ double sh0[128], sh1[128], sh2[128];
    double a = 0.0, b = 0.0, c = 0.0;
    if (tid < 64) a = g_pintra[tid];
    if (tid < 16) { b = g_psp[tid]; c = g_peq[tid]; }
    sh0[tid] = a; sh1[tid] = b; sh2[tid] = c;
    __syncthreads();
    for (int s = 64; s; s >>= 1) {
        if (tid < s) {
            sh0[tid] += sh0[tid + s];
            sh1[tid] += sh1[tid + s];
            sh2[tid] += sh2[tid + s];
        }
        __syncthreads();
    }
    if (tid == 0) {
        double inter_loss = 1.0 - (sh2[0] / (double)BSZ + sh1[0] / (double)BSZ);
        double intra_loss = 1.0 - sh0[0] / (double)CSZ;
        out[0] = (float)(inter_loss + intra_loss);
    }
}

// ---------------- launch ------------------------------------------------------
extern "C" void kernel_launch(void* const* d_in, const int* in_sizes, int n_in,
                              void* d_out, int out_size) {
    const float* zs = (const float*)d_in[0];
    const float* zt = (const float*)d_in[1];

    dim3 g1(BSZ, 2);
    k_rowstats<<<g1, 256>>>(zs, zt);

    dim3 g2(16, 128);
    k_colstats<<<g2, 256>>>(zs, zt);

    k_partial<<<80, 256>>>();
    k_combine<<<1, 128>>>((float*)d_out);
}

// round 7
// speedup vs baseline: 1.7833x; 1.0127x over previous
#include <cuda_runtime.h>
#include <math.h>

#define BSZ 4096
#define CSZ 16000
#define C4  4000
#define NM1 15999.0f
#define LOG2E 1.4426950408889634f
#define BIGP 2e37f

// ---------------- scratch (device globals) ----------------------------------
__device__ float    g_c[2][BSZ];           // -log2(Z)
__device__ float    g_m[2][BSZ];           // row max
__device__ int      g_cnt[2][BSZ][10];
__device__ int      g_amax[2][BSZ];
__device__ float    g_s1[CSZ], g_s2[CSZ], g_t1[CSZ], g_t2[CSZ], g_st[CSZ];
__device__ double   g_acc[3];              // intra, spearman, equal
__device__ unsigned g_tickets;

static __device__ __forceinline__ float ex2f(float x) {
    float y;
    asm("ex2.approx.f32 %0, %1;" : "=f"(y) : "f"(x));
    return y;
}

// 1.0f iff x < u (uB = u*BIGP precomputed), via saturating FMA (fma pipe, no preds)
static __device__ __forceinline__ float satlt(float x, float uB) {
    float t;
    asm("fma.rn.sat.f32 %0, %1, %2, %3;" : "=f"(t) : "f"(x), "f"(-BIGP), "f"(uB));
    return t;
}

// monotone unsigned key: (a<b as float) == (key(a)<key(b) unsigned)
static __device__ __forceinline__ unsigned fkey(float x) {
    int i = __float_as_int(x);
    return (unsigned)(i ^ ((i >> 31) | 0x80000000));
}

// ---------------- kernel 1: row pass (max, sum-exp, 10 rank counts) ----------
__global__ void __launch_bounds__(256) k_rowstats(const float* __restrict__ zs,
                                                  const float* __restrict__ zt) {
    const int b = blockIdx.x;
    const int t = blockIdx.y;

    // ---- folded init ----
    if (threadIdx.x == 10) g_amax[t][b] = 0x7FFFFFFF;
    if (threadIdx.x < 10) {
        int i = (b * 2 + t) * 10 + threadIdx.x;
        if (i < CSZ) {
            g_s1[i] = 0.f; g_s2[i] = 0.f; g_t1[i] = 0.f; g_t2[i] = 0.f; g_st[i] = 0.f;
        }
    }
    if (b == 0 && t == 0) {
        if (threadIdx.x == 11) { g_acc[0] = 0.0; g_acc[1] = 0.0; g_acc[2] = 0.0; }
        if (threadIdx.x == 12) g_tickets = 0u;
    }

    const float* row = (t == 0 ? zs : zt) + (size_t)b * CSZ;
    const float4* row4 = (const float4*)row;

    float uB[5];
    unsigned uk[5];
#pragma unroll
    for (int j = 0; j < 5; j++) uB[j] = row[j] * BIGP;        // broadcast, L1 hit
#pragma unroll
    for (int j = 0; j < 5; j++) uk[j] = fkey(row[5 + j]);

    float mx = -1e30f;
    float sm0 = 0.f, sm1 = 0.f, sm2 = 0.f, sm3 = 0.f;
    float fc[5] = {0.f, 0.f, 0.f, 0.f, 0.f};
    int   ic[5] = {0, 0, 0, 0, 0};

#pragma unroll 4
    for (int i = threadIdx.x; i < C4; i += 256) {
        float4 v = row4[i];                                    // default caching (L2 keep)
        sm0 += ex2f(v.x * LOG2E);
        sm1 += ex2f(v.y * LOG2E);
        sm2 += ex2f(v.z * LOG2E);
        sm3 += ex2f(v.w * LOG2E);
        mx = fmaxf(mx, fmaxf(fmaxf(v.x, v.y), fmaxf(v.z, v.w)));
        unsigned kx = fkey(v.x), ky = fkey(v.y), kz = fkey(v.z), kw = fkey(v.w);
#pragma unroll
        for (int j = 0; j < 5; j++) {
            fc[j] += satlt(v.x, uB[j]);
            fc[j] += satlt(v.y, uB[j]);
            fc[j] += satlt(v.z, uB[j]);
            fc[j] += satlt(v.w, uB[j]);
            ic[j] += (int)(kx < uk[j]) + (int)(ky < uk[j]) +
                     (int)(kz < uk[j]) + (int)(kw < uk[j]);
        }
    }
    float sm = (sm0 + sm1) + (sm2 + sm3);

    const unsigned FULL = 0xffffffffu;
#pragma unroll
    for (int o = 16; o; o >>= 1) {
        mx = fmaxf(mx, __shfl_xor_sync(FULL, mx, o));
        sm += __shfl_xor_sync(FULL, sm, o);
#pragma unroll
        for (int j = 0; j < 5; j++) fc[j] += __shfl_xor_sync(FULL, fc[j], o);
    }
#pragma unroll
    for (int j = 0; j < 5; j++) ic[j] = __reduce_add_sync(FULL, ic[j]);

    __shared__ float smx[8], ssm[8], sfc[8][5];
    __shared__ int sic[8][5];
    int w = threadIdx.x >> 5, lane = threadIdx.x & 31;
    if (lane == 0) {
        smx[w] = mx; ssm[w] = sm;
#pragma unroll
        for (int j = 0; j < 5; j++) { sfc[w][j] = fc[j]; sic[w][j] = ic[j]; }
    }
    __syncthreads();
    if (threadIdx.x == 0) {
#pragma unroll
        for (int ww = 1; ww < 8; ww++) {
            mx = fmaxf(mx, smx[ww]);
            sm += ssm[ww];
#pragma unroll
            for (int j = 0; j < 5; j++) { fc[j] += sfc[ww][j]; ic[j] += sic[ww][j]; }
        }
        g_m[t][b] = mx;
        g_c[t][b] = -log2f(sm);
#pragma unroll
        for (int j = 0; j < 5; j++) g_cnt[t][b][j] = __float2int_rn(fc[j]);
#pragma unroll
        for (int j = 0; j < 5; j++) g_cnt[t][b][5 + j] = ic[j];
    }
}

// ---------------- kernel 2: column pass (intra stats + argmax) ---------------
// grid (16, 128): 1024 cols per x-block, 32 rows per y-block. Row-block order
// reversed so the first blocks hit rows rowstats left in L2.
__global__ void __launch_bounds__(256) k_colstats(const float* __restrict__ zs,
                                                  const float* __restrict__ zt) {
    const int c = blockIdx.x * 1024 + threadIdx.x * 4;
    if (c >= CSZ) return;
    const int r0 = (127 - blockIdx.y) * 32;

    float a1[4] = {0, 0, 0, 0}, a2[4] = {0, 0, 0, 0};
    float b1[4] = {0, 0, 0, 0}, b2[4] = {0, 0, 0, 0};
    float ab[4] = {0, 0, 0, 0};

#pragma unroll 4
    for (int rr = 0; rr < 32; rr++) {
        const int r = r0 + rr;
        const float cs = g_c[0][r], ct = g_c[1][r];   // uniform
        const float ms = g_m[0][r], mt = g_m[1][r];
        const float4 xs = __ldcs((const float4*)(zs + (size_t)r * CSZ + c));
        const float4 xt = __ldcs((const float4*)(zt + (size_t)r * CSZ + c));
#pragma unroll
        for (int k = 0; k < 4; k++) {
            float xsk = (k == 0 ? xs.x : k == 1 ? xs.y : k == 2 ? xs.z : xs.w);
            float xtk = (k == 0 ? xt.x : k == 1 ? xt.y : k == 2 ? xt.z : xt.w);
            float ys = ex2f(fmaf(xsk, LOG2E, cs));
            float yt = ex2f(fmaf(xtk, LOG2E, ct));
            a1[k] += ys; a2[k] = fmaf(ys, ys, a2[k]);
            b1[k] += yt; b2[k] = fmaf(yt, yt, b2[k]);
            ab[k] = fmaf(ys, yt, ab[k]);
            if (xsk == ms) atomicMin(&g_amax[0][r], c + k);
            if (xtk == mt) atomicMin(&g_amax[1][r], c + k);
        }
    }
#pragma unroll
    for (int k = 0; k < 4; k++) {
        atomicAdd(&g_s1[c + k], a1[k]);
        atomicAdd(&g_s2[c + k], a2[k]);
        atomicAdd(&g_t1[c + k], b1[k]);
        atomicAdd(&g_t2[c + k], b2[k]);
        atomicAdd(&g_st[c + k], ab[k]);
    }
}

// ---------------- kernel 3: fused partial + final reduction ------------------
// blocks 0..63 : intra pearson over 250 columns each
// blocks 64..79: inter spearman/eq over 256 rows each
// last-arriving block computes the final loss.
__global__ void __launch_bounds__(256) k_final(float* __restrict__ out) {
    const int bid = blockIdx.x;
    const int tid = threadIdx.x;
    __shared__ double sh0[256], sh1[256];

    double v0 = 0.0, v1 = 0.0;
    int slot0, slot1 = -1;

    if (bid < 64) {
        slot0 = 0;                                  // intra
        const float invB = 1.f / (float)BSZ;
        int c = bid * 250 + tid;
        if (tid < 250) {
            float s1 = g_s1[c], s2 = g_s2[c], t1 = g_t1[c], t2 = g_t2[c], st = g_st[c];
            float num = st - s1 * t1 * invB;
            float vs = s2 - s1 * s1 * invB;
            float vt = t2 - t1 * t1 * invB;
            float den = sqrtf(fmaxf(vs, 0.f)) * sqrtf(fmaxf(vt, 0.f)) + 1e-8f;
            v0 = (double)(num / den);
        }
    } else {
        slot0 = 1; slot1 = 2;                       // spearman, equal
        const int b = (bid - 64) * 256 + tid;
        const int js = g_amax[0][b], jt = g_amax[1][b];
        v1 = (js == jt) ? 1.0 : 0.0;

        int ms[10], mt[10];
        bool ks[10], kt[10];
        float Ds = 0.f, Qs = 0.f, Dt = 0.f, Qt = 0.f;
#pragma unroll
        for (int i = 0; i < 10; i++) {
            int p = g_cnt[0][b][i];
            ks[i] = (p != js);
            ms[i] = p - (p > js ? 1 : 0);
            float v = (float)(10 - i);
            if (ks[i]) { Ds += v; Qs += v * v; }
            p = g_cnt[1][b][i];
            kt[i] = (p != jt);
            mt[i] = p - (p > jt ? 1 : 0);
            if (kt[i]) { Dt += v; Qt += v * v; }
        }
        float X = 0.f;
#pragma unroll
        for (int i = 0; i < 10; i++) {
#pragma unroll
            for (int k2 = 0; k2 < 10; k2++) {
                if (ks[i] && kt[k2] && (ms[i] == mt[k2]))
                    X += (float)(10 - i) * (float)(10 - k2);
            }
        }
        float num = X - Ds * Dt / NM1;
        float den = sqrtf(fmaxf(Qs - Ds * Ds / NM1, 0.f)) *
                    sqrtf(fmaxf(Qt - Dt * Dt / NM1, 0.f)) + 1e-8f;
        v0 = (double)(num / den);
    }

    sh0[tid] = v0; sh1[tid] = v1;
    __syncthreads();
    for (int s = 128; s; s >>= 1) {
        if (tid < s) { sh0[tid] += sh0[tid + s]; sh1[tid] += sh1[tid + s]; }
        __syncthreads();
    }

    if (tid == 0) {
        atomicAdd(&g_acc[slot0], sh0[0]);
        if (slot1 >= 0) atomicAdd(&g_acc[slot1], sh1[0]);
        __threadfence();
        unsigned ticket = atomicAdd(&g_tickets, 1u);
        if (ticket == 79u) {
            __threadfence();
            double intra = ((volatile double*)g_acc)[0];
            double sp    = ((volatile double*)g_acc)[1];
            double eq    = ((volatile double*)g_acc)[2];
            double inter_loss = 1.0 - (eq / (double)BSZ + sp / (double)BSZ);
            double intra_loss = 1.0 - intra / (double)CSZ;
            out[0] = (float)(inter_loss + intra_loss);
        }
    }
}

// ---------------- launch ------------------------------------------------------
extern "C" void kernel_launch(void* const* d_in, const int* in_sizes, int n_in,
                              void* d_out, int out_size) {
    const float* zs = (const float*)d_in[0];
    const float* zt = (const float*)d_in[1];

    dim3 g1(BSZ, 2);
    k_rowstats<<<g1, 256>>>(zs, zt);

    dim3 g2(16, 128);
    k_colstats<<<g2, 256>>>(zs, zt);

    k_final<<<80, 256>>>((float*)d_out);
}